// round 8
// baseline (speedup 1.0000x reference)
#include <cuda_runtime.h>

#define BATCH 8
#define NROWS 10000
#define CDIM 256
#define CHUNKS 250
#define ROWS_PER_CHUNK 40    // 10000 / 250; 40 = 8*5, no tail
#define LN_EPS 1e-5f

// Scratch (allocation-free rule: __device__ globals)
__device__ float g_partial[BATCH][CHUNKS][CDIM];
__device__ float g_agg[BATCH][CDIM];

// ---------------------------------------------------------------------------
// Kernel 1: partial column sums. grid (BATCH, CHUNKS) = 2000 blocks, 256 thr
// -> 8 CTAs resident per SM (100% occupancy). Thread t: float4-column
// (t&63), row-group (t>>6). 2 accumulators, 5 unrolled pair-iterations
// covering all 40 rows (rg..36+rg step 4).
// ---------------------------------------------------------------------------
__global__ void col_sum_kernel(const float* __restrict__ x) {
    const int b = blockIdx.x;
    const int ch = blockIdx.y;
    const int t = threadIdx.x;
    const int qc = t & 63;       // float4 column 0..63
    const int rg = t >> 6;       // row group 0..3

    const float4* base = (const float4*)(x
        + ((size_t)b * NROWS + (size_t)ch * ROWS_PER_CHUNK) * CDIM) + qc;

    float4 acc0 = make_float4(0.f, 0.f, 0.f, 0.f);
    float4 acc1 = make_float4(0.f, 0.f, 0.f, 0.f);
#pragma unroll
    for (int r = 0; r < ROWS_PER_CHUNK; r += 8) {
        float4 v0 = base[(size_t)(r + rg) * 64];
        float4 v1 = base[(size_t)(r + rg + 4) * 64];
        acc0.x += v0.x; acc0.y += v0.y; acc0.z += v0.z; acc0.w += v0.w;
        acc1.x += v1.x; acc1.y += v1.y; acc1.z += v1.z; acc1.w += v1.w;
    }
    acc0.x += acc1.x; acc0.y += acc1.y; acc0.z += acc1.z; acc0.w += acc1.w;

    __shared__ float4 sh[256];
    sh[t] = acc0;
    __syncthreads();
    if (t < 64) {
        float4 a = sh[t];
        float4 c1 = sh[t + 64];
        float4 c2 = sh[t + 128];
        float4 c3 = sh[t + 192];
        a.x += c1.x + c2.x + c3.x;
        a.y += c1.y + c2.y + c3.y;
        a.z += c1.z + c2.z + c3.z;
        a.w += c1.w + c2.w + c3.w;
        ((float4*)&g_partial[b][ch][0])[t] = a;
    }
}

// ---------------------------------------------------------------------------
// Kernel 2: finish mean + tiny GEMM  agg[b][c] = dot(mean[b,:], W[c,:]) + bias
// ---------------------------------------------------------------------------
__global__ void mean_gemm_kernel(const float* __restrict__ W,
                                 const float* __restrict__ bias) {
    const int b = blockIdx.x;
    const int t = threadIdx.x;
    __shared__ float smean[CDIM];

    float s = 0.0f;
#pragma unroll 10
    for (int j = 0; j < CHUNKS; ++j) s += g_partial[b][j][t];
    smean[t] = s * (1.0f / (float)NROWS);
    __syncthreads();

    const int warp = t >> 5;
    const int lane = t & 31;
    for (int c = warp; c < CDIM; c += 8) {
        const float* wr = W + (size_t)c * CDIM;
        float d = 0.0f;
#pragma unroll
        for (int k = lane; k < CDIM; k += 32) {
            d += wr[k] * smean[k];
        }
#pragma unroll
        for (int off = 16; off > 0; off >>= 1)
            d += __shfl_down_sync(0xffffffffu, d, off);
        if (lane == 0) g_agg[b][c] = d + bias[c];
    }
}

// ---------------------------------------------------------------------------
// Kernel 3: fused residual + LayerNorm, software-pipelined, REVERSED block
// order (early blocks read the rows col_sum touched last -> hottest in L2),
// streaming stores (__stcs) so out writes don't evict L2-resident x.
// Block = 256 threads = 8 warps, 80 rows per block (10 rows/warp, 5 iters
// of 2 rows). 10000 = 80*125 so no block crosses a batch boundary.
// ---------------------------------------------------------------------------
__global__ void resid_ln_kernel(const float* __restrict__ x,
                                const float* __restrict__ gamma,
                                const float* __restrict__ beta,
                                float* __restrict__ out) {
    const int t = threadIdx.x;
    const int warp = t >> 5;
    const int lane = t & 31;
    // Reverse: block 0 takes the LAST 80 rows
    const int nblk = (BATCH * NROWS) / 80;   // 1000
    const long blockRow0 = (long)(nblk - 1 - blockIdx.x) * 80;
    const int b = (int)(blockRow0 / NROWS);   // uniform within block

    __shared__ float sh_agg[CDIM];
    __shared__ float sh_g[CDIM];
    __shared__ float sh_b[CDIM];
    sh_agg[t] = g_agg[b][t];
    sh_g[t] = gamma[t];
    sh_b[t] = beta[t];
    __syncthreads();

    const float4 ag0 = ((const float4*)sh_agg)[lane * 2 + 0];
    const float4 ag1 = ((const float4*)sh_agg)[lane * 2 + 1];
    const float4 g0 = ((const float4*)sh_g)[lane * 2 + 0];
    const float4 g1 = ((const float4*)sh_g)[lane * 2 + 1];
    const float4 b0 = ((const float4*)sh_b)[lane * 2 + 0];
    const float4 b1 = ((const float4*)sh_b)[lane * 2 + 1];

    const long row0 = blockRow0 + (long)warp * 10;
    const int li = lane * 2;

    // Prologue: loads for rows row0, row0+1
    float4 c00, c01, c10, c11;
    {
        const float4* xr0 = (const float4*)(x + row0 * (long)CDIM);
        const float4* xr1 = (const float4*)(x + (row0 + 1) * (long)CDIM);
        c00 = xr0[li]; c01 = xr0[li + 1];
        c10 = xr1[li]; c11 = xr1[li + 1];
    }

#pragma unroll
    for (int it = 0; it < 5; ++it) {
        // Issue next iteration's loads first (sustained MLP)
        float4 n00, n01, n10, n11;
        if (it < 4) {
            const long r = row0 + 2 * (it + 1);
            const float4* xr0 = (const float4*)(x + r * (long)CDIM);
            const float4* xr1 = (const float4*)(x + (r + 1) * (long)CDIM);
            n00 = xr0[li]; n01 = xr0[li + 1];
            n10 = xr1[li]; n11 = xr1[li + 1];
        }

        // Compute current two rows
        float ya[8], yb[8];
        ya[0] = c00.x + ag0.x; ya[1] = c00.y + ag0.y;
        ya[2] = c00.z + ag0.z; ya[3] = c00.w + ag0.w;
        ya[4] = c01.x + ag1.x; ya[5] = c01.y + ag1.y;
        ya[6] = c01.z + ag1.z; ya[7] = c01.w + ag1.w;
        yb[0] = c10.x + ag0.x; yb[1] = c10.y + ag0.y;
        yb[2] = c10.z + ag0.z; yb[3] = c10.w + ag0.w;
        yb[4] = c11.x + ag1.x; yb[5] = c11.y + ag1.y;
        yb[6] = c11.z + ag1.z; yb[7] = c11.w + ag1.w;

        float s0 = 0.f, ss0 = 0.f, s1 = 0.f, ss1 = 0.f;
#pragma unroll
        for (int i = 0; i < 8; ++i) {
            s0 += ya[i]; ss0 += ya[i] * ya[i];
            s1 += yb[i]; ss1 += yb[i] * yb[i];
        }
#pragma unroll
        for (int off = 16; off > 0; off >>= 1) {
            s0  += __shfl_xor_sync(0xffffffffu, s0, off);
            ss0 += __shfl_xor_sync(0xffffffffu, ss0, off);
            s1  += __shfl_xor_sync(0xffffffffu, s1, off);
            ss1 += __shfl_xor_sync(0xffffffffu, ss1, off);
        }

        const float inv = 1.0f / (float)CDIM;
        const float mu0 = s0 * inv;
        const float mu1 = s1 * inv;
        const float r0 = rsqrtf(ss0 * inv - mu0 * mu0 + LN_EPS);
        const float r1 = rsqrtf(ss1 * inv - mu1 * mu1 + LN_EPS);

        const long rcur = row0 + 2 * it;
        float4* or0 = (float4*)(out + rcur * (long)CDIM);
        float4* or1 = (float4*)(out + (rcur + 1) * (long)CDIM);
        float4 o;
        o.x = (ya[0] - mu0) * r0 * g0.x + b0.x;
        o.y = (ya[1] - mu0) * r0 * g0.y + b0.y;
        o.z = (ya[2] - mu0) * r0 * g0.z + b0.z;
        o.w = (ya[3] - mu0) * r0 * g0.w + b0.w;
        __stcs(&or0[li], o);
        o.x = (ya[4] - mu0) * r0 * g1.x + b1.x;
        o.y = (ya[5] - mu0) * r0 * g1.y + b1.y;
        o.z = (ya[6] - mu0) * r0 * g1.z + b1.z;
        o.w = (ya[7] - mu0) * r0 * g1.w + b1.w;
        __stcs(&or0[li + 1], o);
        o.x = (yb[0] - mu1) * r1 * g0.x + b0.x;
        o.y = (yb[1] - mu1) * r1 * g0.y + b0.y;
        o.z = (yb[2] - mu1) * r1 * g0.z + b0.z;
        o.w = (yb[3] - mu1) * r1 * g0.w + b0.w;
        __stcs(&or1[li], o);
        o.x = (yb[4] - mu1) * r1 * g1.x + b1.x;
        o.y = (yb[5] - mu1) * r1 * g1.y + b1.y;
        o.z = (yb[6] - mu1) * r1 * g1.z + b1.z;
        o.w = (yb[7] - mu1) * r1 * g1.w + b1.w;
        __stcs(&or1[li + 1], o);

        // Rotate pipeline
        c00 = n00; c01 = n01; c10 = n10; c11 = n11;
    }
}

extern "C" void kernel_launch(void* const* d_in, const int* in_sizes, int n_in,
                              void* d_out, int out_size) {
    const float* x     = (const float*)d_in[0];
    const float* W     = (const float*)d_in[1];
    const float* bias  = (const float*)d_in[2];
    const float* gamma = (const float*)d_in[3];
    const float* beta  = (const float*)d_in[4];
    float* out = (float*)d_out;

    dim3 g1(BATCH, CHUNKS);
    col_sum_kernel<<<g1, 256>>>(x);
    mean_gemm_kernel<<<BATCH, CDIM>>>(W, bias);
    resid_ln_kernel<<<(BATCH * NROWS) / 80, 256>>>(x, gamma, beta, out);
}

// round 10
// speedup vs baseline: 1.0892x; 1.0892x over previous
#include <cuda_runtime.h>

#define BATCH 8
#define NROWS 10000
#define CDIM 256
#define CHUNKS 100
#define ROWS_PER_CHUNK 100   // 10000 / 100
#define LN_EPS 1e-5f

// Scratch (allocation-free rule: __device__ globals)
__device__ float g_partial[BATCH][CHUNKS][CDIM];
__device__ float g_agg[BATCH][CDIM];

// 256-bit load with L2 evict_last (high retention) — the only load width
// ptxas accepts the evict hint on for sm_103a.
__device__ __forceinline__ void ldg32B_evict_last(const void* p, float4& a, float4& b) {
    asm volatile("ld.global.L2::evict_last.v8.b32 {%0,%1,%2,%3,%4,%5,%6,%7}, [%8];"
                 : "=f"(a.x), "=f"(a.y), "=f"(a.z), "=f"(a.w),
                   "=f"(b.x), "=f"(b.y), "=f"(b.z), "=f"(b.w)
                 : "l"(p));
}

// ---------------------------------------------------------------------------
// Kernel 1: partial column sums, 32B lanes + L2 evict_last on x.
// grid (BATCH, CHUNKS) = 800 blocks, 256 thr. Thread t: 32B-column (t&31),
// row-group (t>>5, 0..7). Row = 1024B. Main loop: 6 pair-iterations cover
// rows [0,96) at stride 8; tail rows 96..99 covered by rg<4.
// ---------------------------------------------------------------------------
__global__ void col_sum_kernel(const float* __restrict__ x) {
    const int b = blockIdx.x;
    const int ch = blockIdx.y;
    const int t = threadIdx.x;
    const int qc = t & 31;       // 32-byte column 0..31
    const int rg = t >> 5;       // row group 0..7

    const char* base = (const char*)(x
        + ((size_t)b * NROWS + (size_t)ch * ROWS_PER_CHUNK) * CDIM) + qc * 32;

    float4 a0 = make_float4(0.f, 0.f, 0.f, 0.f);
    float4 a1 = make_float4(0.f, 0.f, 0.f, 0.f);
    float4 b0 = make_float4(0.f, 0.f, 0.f, 0.f);
    float4 b1 = make_float4(0.f, 0.f, 0.f, 0.f);
#pragma unroll
    for (int r = 0; r < 96; r += 16) {
        float4 u0, u1, v0, v1;
        ldg32B_evict_last(base + (size_t)(r + rg) * 1024, u0, u1);
        ldg32B_evict_last(base + (size_t)(r + rg + 8) * 1024, v0, v1);
        a0.x += u0.x; a0.y += u0.y; a0.z += u0.z; a0.w += u0.w;
        a1.x += u1.x; a1.y += u1.y; a1.z += u1.z; a1.w += u1.w;
        b0.x += v0.x; b0.y += v0.y; b0.z += v0.z; b0.w += v0.w;
        b1.x += v1.x; b1.y += v1.y; b1.z += v1.z; b1.w += v1.w;
    }
    if (rg < 4) {  // tail rows 96..99
        float4 u0, u1;
        ldg32B_evict_last(base + (size_t)(96 + rg) * 1024, u0, u1);
        a0.x += u0.x; a0.y += u0.y; a0.z += u0.z; a0.w += u0.w;
        a1.x += u1.x; a1.y += u1.y; a1.z += u1.z; a1.w += u1.w;
    }
    a0.x += b0.x; a0.y += b0.y; a0.z += b0.z; a0.w += b0.w;
    a1.x += b1.x; a1.y += b1.y; a1.z += b1.z; a1.w += b1.w;

    // Shared reduce across 8 row-groups. Layout: sh[rg*64 + qc*2 + half].
    __shared__ float4 sh[512];
    sh[rg * 64 + qc * 2 + 0] = a0;
    sh[rg * 64 + qc * 2 + 1] = a1;
    __syncthreads();
    if (t < 64) {
        float4 a = sh[t];
#pragma unroll
        for (int g = 1; g < 8; ++g) {
            float4 c = sh[g * 64 + t];
            a.x += c.x; a.y += c.y; a.z += c.z; a.w += c.w;
        }
        ((float4*)&g_partial[b][ch][0])[t] = a;
    }
}

// ---------------------------------------------------------------------------
// Kernel 2: finish mean + tiny GEMM  agg[b][c] = dot(mean[b,:], W[c,:]) + bias
// ---------------------------------------------------------------------------
__global__ void mean_gemm_kernel(const float* __restrict__ W,
                                 const float* __restrict__ bias) {
    const int b = blockIdx.x;
    const int t = threadIdx.x;
    __shared__ float smean[CDIM];

    float s = 0.0f;
#pragma unroll 10
    for (int j = 0; j < CHUNKS; ++j) s += g_partial[b][j][t];
    smean[t] = s * (1.0f / (float)NROWS);
    __syncthreads();

    const int warp = t >> 5;
    const int lane = t & 31;
    for (int c = warp; c < CDIM; c += 8) {
        const float* wr = W + (size_t)c * CDIM;
        float d = 0.0f;
#pragma unroll
        for (int k = lane; k < CDIM; k += 32) {
            d += wr[k] * smean[k];
        }
#pragma unroll
        for (int off = 16; off > 0; off >>= 1)
            d += __shfl_down_sync(0xffffffffu, d, off);
        if (lane == 0) g_agg[b][c] = d + bias[c];
    }
}

// ---------------------------------------------------------------------------
// Kernel 3: fused residual + LayerNorm, software-pipelined (R7 exact).
// Block = 256 threads = 8 warps, 80 rows per block (10 rows/warp, 5 iters
// of 2 rows). Natural block order, plain loads/stores.
// ---------------------------------------------------------------------------
__global__ void resid_ln_kernel(const float* __restrict__ x,
                                const float* __restrict__ gamma,
                                const float* __restrict__ beta,
                                float* __restrict__ out) {
    const int t = threadIdx.x;
    const int warp = t >> 5;
    const int lane = t & 31;
    const long blockRow0 = (long)blockIdx.x * 80;
    const int b = (int)(blockRow0 / NROWS);   // uniform within block

    __shared__ float sh_agg[CDIM];
    __shared__ float sh_g[CDIM];
    __shared__ float sh_b[CDIM];
    sh_agg[t] = g_agg[b][t];
    sh_g[t] = gamma[t];
    sh_b[t] = beta[t];
    __syncthreads();

    const float4 ag0 = ((const float4*)sh_agg)[lane * 2 + 0];
    const float4 ag1 = ((const float4*)sh_agg)[lane * 2 + 1];
    const float4 g0 = ((const float4*)sh_g)[lane * 2 + 0];
    const float4 g1 = ((const float4*)sh_g)[lane * 2 + 1];
    const float4 b0 = ((const float4*)sh_b)[lane * 2 + 0];
    const float4 b1 = ((const float4*)sh_b)[lane * 2 + 1];

    const long row0 = blockRow0 + (long)warp * 10;
    const int li = lane * 2;

    // Prologue: loads for rows row0, row0+1
    float4 c00, c01, c10, c11;
    {
        const float4* xr0 = (const float4*)(x + row0 * (long)CDIM);
        const float4* xr1 = (const float4*)(x + (row0 + 1) * (long)CDIM);
        c00 = xr0[li]; c01 = xr0[li + 1];
        c10 = xr1[li]; c11 = xr1[li + 1];
    }

#pragma unroll
    for (int it = 0; it < 5; ++it) {
        // Issue next iteration's loads first (sustained MLP)
        float4 n00, n01, n10, n11;
        if (it < 4) {
            const long r = row0 + 2 * (it + 1);
            const float4* xr0 = (const float4*)(x + r * (long)CDIM);
            const float4* xr1 = (const float4*)(x + (r + 1) * (long)CDIM);
            n00 = xr0[li]; n01 = xr0[li + 1];
            n10 = xr1[li]; n11 = xr1[li + 1];
        }

        // Compute current two rows
        float ya[8], yb[8];
        ya[0] = c00.x + ag0.x; ya[1] = c00.y + ag0.y;
        ya[2] = c00.z + ag0.z; ya[3] = c00.w + ag0.w;
        ya[4] = c01.x + ag1.x; ya[5] = c01.y + ag1.y;
        ya[6] = c01.z + ag1.z; ya[7] = c01.w + ag1.w;
        yb[0] = c10.x + ag0.x; yb[1] = c10.y + ag0.y;
        yb[2] = c10.z + ag0.z; yb[3] = c10.w + ag0.w;
        yb[4] = c11.x + ag1.x; yb[5] = c11.y + ag1.y;
        yb[6] = c11.z + ag1.z; yb[7] = c11.w + ag1.w;

        float s0 = 0.f, ss0 = 0.f, s1 = 0.f, ss1 = 0.f;
#pragma unroll
        for (int i = 0; i < 8; ++i) {
            s0 += ya[i]; ss0 += ya[i] * ya[i];
            s1 += yb[i]; ss1 += yb[i] * yb[i];
        }
#pragma unroll
        for (int off = 16; off > 0; off >>= 1) {
            s0  += __shfl_xor_sync(0xffffffffu, s0, off);
            ss0 += __shfl_xor_sync(0xffffffffu, ss0, off);
            s1  += __shfl_xor_sync(0xffffffffu, s1, off);
            ss1 += __shfl_xor_sync(0xffffffffu, ss1, off);
        }

        const float inv = 1.0f / (float)CDIM;
        const float mu0 = s0 * inv;
        const float mu1 = s1 * inv;
        const float r0 = rsqrtf(ss0 * inv - mu0 * mu0 + LN_EPS);
        const float r1 = rsqrtf(ss1 * inv - mu1 * mu1 + LN_EPS);

        const long rcur = row0 + 2 * it;
        float4* or0 = (float4*)(out + rcur * (long)CDIM);
        float4* or1 = (float4*)(out + (rcur + 1) * (long)CDIM);
        float4 o;
        o.x = (ya[0] - mu0) * r0 * g0.x + b0.x;
        o.y = (ya[1] - mu0) * r0 * g0.y + b0.y;
        o.z = (ya[2] - mu0) * r0 * g0.z + b0.z;
        o.w = (ya[3] - mu0) * r0 * g0.w + b0.w;
        or0[li] = o;
        o.x = (ya[4] - mu0) * r0 * g1.x + b1.x;
        o.y = (ya[5] - mu0) * r0 * g1.y + b1.y;
        o.z = (ya[6] - mu0) * r0 * g1.z + b1.z;
        o.w = (ya[7] - mu0) * r0 * g1.w + b1.w;
        or0[li + 1] = o;
        o.x = (yb[0] - mu1) * r1 * g0.x + b0.x;
        o.y = (yb[1] - mu1) * r1 * g0.y + b0.y;
        o.z = (yb[2] - mu1) * r1 * g0.z + b0.z;
        o.w = (yb[3] - mu1) * r1 * g0.w + b0.w;
        or1[li] = o;
        o.x = (yb[4] - mu1) * r1 * g1.x + b1.x;
        o.y = (yb[5] - mu1) * r1 * g1.y + b1.y;
        o.z = (yb[6] - mu1) * r1 * g1.z + b1.z;
        o.w = (yb[7] - mu1) * r1 * g1.w + b1.w;
        or1[li + 1] = o;

        // Rotate pipeline
        c00 = n00; c01 = n01; c10 = n10; c11 = n11;
    }
}

extern "C" void kernel_launch(void* const* d_in, const int* in_sizes, int n_in,
                              void* d_out, int out_size) {
    const float* x     = (const float*)d_in[0];
    const float* W     = (const float*)d_in[1];
    const float* bias  = (const float*)d_in[2];
    const float* gamma = (const float*)d_in[3];
    const float* beta  = (const float*)d_in[4];
    float* out = (float*)d_out;

    dim3 g1(BATCH, CHUNKS);
    col_sum_kernel<<<g1, 256>>>(x);
    mean_gemm_kernel<<<BATCH, CDIM>>>(W, bias);
    resid_ln_kernel<<<(BATCH * NROWS) / 80, 256>>>(x, gamma, beta, out);
}